// round 10
// baseline (speedup 1.0000x reference)
#include <cuda_runtime.h>

static constexpr int KC = 5;
static constexpr int DC = 10;
static constexpr int NBINS = 16384;
static constexpr float EPS_MARGIN = 1e-4f;

__device__ unsigned char g_lut[NBINS];

// strict < keeps first occurrence (matches jnp.argmin); scores = {0, g1..g4}
__device__ __forceinline__ float select_idx(float g1, float g2, float g3, float g4) {
    float best = 0.0f, idx = 0.0f;
    idx  = (g1 < best) ? 1.0f : idx;  best = fminf(g1, best);
    idx  = (g2 < best) ? 2.0f : idx;  best = fminf(g2, best);
    idx  = (g3 < best) ? 3.0f : idx;  best = fminf(g3, best);
    idx  = (g4 < best) ? 4.0f : idx;  best = fminf(g4, best);
    return idx;
}

// ---------------- Kernel A: LUT builder ----------------
__global__ __launch_bounds__(256) void vq_build_lut(const float* __restrict__ emb)
{
    int bin = blockIdx.x * blockDim.x + threadIdx.x;
    if (bin >= NBINS) return;

    // Difference-poly coefficients vs code 0 (EXACT same expressions as fallback)
    float c[KC - 1][DC], d[KC - 1];
    {
        float e0[DC], s0 = 0.0f;
        #pragma unroll
        for (int i = 0; i < DC; i++) { e0[i] = emb[i]; s0 = fmaf(e0[i], e0[i], s0); }
        #pragma unroll
        for (int k = 1; k < KC; k++) {
            float sk = 0.0f;
            #pragma unroll
            for (int i = 0; i < DC; i++) {
                float e = emb[k * DC + i];
                sk = fmaf(e, e, sk);
                c[k - 1][i] = -2.0f * (e - e0[i]);
            }
            d[k - 1] = sk - s0;
        }
    }

    // Dilated 7-point agreement + margin over [bin-0.25, bin+1.25]
    const float offs[7] = {-0.25f, 0.0f, 0.25f, 0.5f, 0.75f, 1.0f, 1.25f};
    int w0 = -1;
    bool ok = true;
    #pragma unroll
    for (int t = 0; t < 7; t++) {
        float v = ((float)bin + offs[t]) * (1.0f / (float)NBINS);
        float sc[KC];
        sc[0] = 0.0f;
        #pragma unroll
        for (int k = 0; k < KC - 1; k++) {
            float h = c[k][DC - 1];
            #pragma unroll
            for (int j = DC - 2; j >= 0; j--) h = fmaf(h, v, c[k][j]);
            sc[k + 1] = fmaf(h, v, d[k]);
        }
        int w = 0; float best = sc[0];
        #pragma unroll
        for (int k = 1; k < KC; k++) if (sc[k] < best) { best = sc[k]; w = k; }
        float second = 3.4e38f;
        #pragma unroll
        for (int k = 0; k < KC; k++) if (k != w) second = fminf(second, sc[k]);
        if (t == 0) w0 = w;
        ok = ok && (w == w0) && (second - best > EPS_MARGIN);
    }
    // Edge bins always sentinel: clamped out-of-range values take the exact path.
    if (bin == 0 || bin == NBINS - 1) ok = false;
    g_lut[bin] = ok ? (unsigned char)w0 : (unsigned char)255;
}

// ---------------- Kernel B: LUT-mapped quantize ----------------
__global__ __launch_bounds__(256, 6) void vq_map(
    const float* __restrict__ x, const float* __restrict__ emb,
    float* __restrict__ out, int n)
{
    __shared__ unsigned char slut[NBINS];
    __shared__ float scoef[(KC - 1) * DC + (KC - 1)];

    {
        const uint4* src = (const uint4*)g_lut;
        uint4* dst = (uint4*)slut;
        #pragma unroll
        for (int i = threadIdx.x; i < NBINS / 16; i += 256) dst[i] = src[i];
    }
    if (threadIdx.x < (KC - 1) * DC) {
        int k = threadIdx.x / DC + 1, j = threadIdx.x % DC;
        scoef[threadIdx.x] = -2.0f * (emb[k * DC + j] - emb[j]);
    } else if (threadIdx.x < (KC - 1) * DC + (KC - 1)) {
        int k = threadIdx.x - (KC - 1) * DC + 1;
        float sk = 0.0f, s0 = 0.0f;
        #pragma unroll
        for (int i = 0; i < DC; i++) {
            float ek = emb[k * DC + i], e0 = emb[i];
            sk = fmaf(ek, ek, sk);
            s0 = fmaf(e0, e0, s0);
        }
        scoef[threadIdx.x] = sk - s0;
    }
    __syncthreads();

    auto fallback = [&](float v) -> float {
        float g[KC - 1];
        #pragma unroll
        for (int k = 0; k < KC - 1; k++) {
            float h = scoef[k * DC + DC - 1];
            #pragma unroll
            for (int j = DC - 2; j >= 0; j--) h = fmaf(h, v, scoef[k * DC + j]);
            g[k] = fmaf(h, v, scoef[(KC - 1) * DC + k]);
        }
        return select_idx(g[0], g[1], g[2], g[3]);
    };

    // Fast lookup: FMUL, F2I, IMNMX clamp, LDS.u8. Sentinel (255) => exact path.
    auto lookup = [&](float v) -> unsigned {
        int b = (int)(v * (float)NBINS);
        b = max(b, 0);
        b = min(b, NBINS - 1);
        return (unsigned)slut[b];
    };

    const int n4 = n >> 2;
    const float4* __restrict__ x4 = (const float4*)x;
    float4* __restrict__ o4 = (float4*)out;
    const int stride = gridDim.x * blockDim.x;
    int i = blockIdx.x * blockDim.x + threadIdx.x;

    float4 cur;
    if (i < n4) cur = x4[i];

    for (; i < n4; i += stride) {
        int nx = i + stride;
        float4 nxt;
        if (nx < n4) nxt = x4[nx];   // depth-1 prefetch overlaps the LDS chain

        unsigned c0 = lookup(cur.x);
        unsigned c1 = lookup(cur.y);
        unsigned c2 = lookup(cur.z);
        unsigned c3 = lookup(cur.w);

        float r0 = (float)c0, r1 = (float)c1, r2 = (float)c2, r3 = (float)c3;
        if ((c0 | c1 | c2 | c3) & 0x80u) {     // rare: exact polynomial path
            if (c0 == 255u) r0 = fallback(cur.x);
            if (c1 == 255u) r1 = fallback(cur.y);
            if (c2 == 255u) r2 = fallback(cur.z);
            if (c3 == 255u) r3 = fallback(cur.w);
        }
        o4[i] = make_float4(r0, r1, r2, r3);
        cur = nxt;
    }

    // Scalar tail (n % 4): exact fallback.
    for (int t = (n4 << 2) + blockIdx.x * blockDim.x + threadIdx.x; t < n; t += stride)
        out[t] = fallback(x[t]);
}

extern "C" void kernel_launch(void* const* d_in, const int* in_sizes, int n_in,
                              void* d_out, int out_size)
{
    const float* x   = (const float*)d_in[0];
    const float* emb = (const float*)d_in[1];
    if (n_in >= 2 && in_sizes[0] == KC * DC && in_sizes[1] != KC * DC) {
        x   = (const float*)d_in[1];
        emb = (const float*)d_in[0];
    }
    float* out = (float*)d_out;
    int n = out_size;

    vq_build_lut<<<NBINS / 256, 256>>>(emb);
    vq_map<<<888, 256>>>(x, emb, out, n);   // 6 CTAs/SM, one wave
}

// round 11
// speedup vs baseline: 2.8227x; 2.8227x over previous
#include <cuda_runtime.h>

static constexpr int KC = 5;
static constexpr int DC = 10;
static constexpr int NBINS = 16384;
static constexpr float EPS_MARGIN = 1e-4f;

__device__ unsigned char g_lut[NBINS];

__device__ __constant__ int PAIR_A[10] = {0,0,0,0,1,1,1,2,2,3};
__device__ __constant__ int PAIR_B[10] = {1,2,3,4,2,3,4,3,4,4};
__device__ __constant__ int PAIR_OFF[4] = {0,4,7,9};   // p = OFF[kA]+kB-kA-1

// strict < keeps first occurrence (matches jnp.argmin); scores = {0, g1..g4}
__device__ __forceinline__ float select_idx(float g1, float g2, float g3, float g4) {
    float best = 0.0f, idx = 0.0f;
    idx  = (g1 < best) ? 1.0f : idx;  best = fminf(g1, best);
    idx  = (g2 < best) ? 2.0f : idx;  best = fminf(g2, best);
    idx  = (g3 < best) ? 3.0f : idx;  best = fminf(g3, best);
    idx  = (g4 < best) ? 4.0f : idx;  best = fminf(g4, best);
    return idx;
}

// ---------------- Kernel A: LUT builder with pair classification ----------------
__global__ __launch_bounds__(256) void vq_build_lut(const float* __restrict__ emb)
{
    int bin = blockIdx.x * blockDim.x + threadIdx.x;
    if (bin >= NBINS) return;

    float c[KC - 1][DC], d[KC - 1];
    {
        float e0[DC], s0 = 0.0f;
        #pragma unroll
        for (int i = 0; i < DC; i++) { e0[i] = emb[i]; s0 = fmaf(e0[i], e0[i], s0); }
        #pragma unroll
        for (int k = 1; k < KC; k++) {
            float sk = 0.0f;
            #pragma unroll
            for (int i = 0; i < DC; i++) {
                float e = emb[k * DC + i];
                sk = fmaf(e, e, sk);
                c[k - 1][i] = -2.0f * (e - e0[i]);
            }
            d[k - 1] = sk - s0;
        }
    }

    // 7 dilated samples over [bin-0.25, bin+1.25]
    const float offs[7] = {-0.25f, 0.0f, 0.25f, 0.5f, 0.75f, 1.0f, 1.25f};
    float S[7][KC];
    unsigned mask = 0;
    #pragma unroll
    for (int t = 0; t < 7; t++) {
        float v = ((float)bin + offs[t]) * (1.0f / (float)NBINS);
        S[t][0] = 0.0f;
        #pragma unroll
        for (int k = 0; k < KC - 1; k++) {
            float h = c[k][DC - 1];
            #pragma unroll
            for (int j = DC - 2; j >= 0; j--) h = fmaf(h, v, c[k][j]);
            S[t][k + 1] = fmaf(h, v, d[k]);
        }
        int w = 0; float best = S[t][0];
        #pragma unroll
        for (int k = 1; k < KC; k++) if (S[t][k] < best) { best = S[t][k]; w = k; }
        int r = -1; float sec = 3.4e38f;
        #pragma unroll
        for (int k = 0; k < KC; k++)
            if (k != w && S[t][k] < sec) { sec = S[t][k]; r = k; }
        mask |= 1u << w;
        if (sec - best <= EPS_MARGIN) mask |= 1u << r;   // runner-up within margin
    }

    unsigned char byte = 255;
    int pc = __popc(mask);
    if (bin == 0 || bin == NBINS - 1) {
        byte = 255;                                       // edges: exact path
    } else if (pc == 1) {
        byte = (unsigned char)(__ffs(mask) - 1);          // definite winner
    } else if (pc == 2) {
        int kA = __ffs(mask) - 1;
        int kB = 31 - __clz(mask);
        bool ok = true;
        #pragma unroll
        for (int t = 0; t < 7; t++) {
            float minIn = fminf(S[t][kA], S[t][kB]);
            float minOut = 3.4e38f;
            #pragma unroll
            for (int k = 0; k < KC; k++)
                if (!(mask & (1u << k))) minOut = fminf(minOut, S[t][k]);
            ok = ok && (minOut - minIn > EPS_MARGIN);
        }
        if (ok) byte = (unsigned char)(128 + PAIR_OFF[kA] + kB - kA - 1);
    }
    g_lut[bin] = byte;
}

// ---------------- Kernel B: LUT-mapped quantize with pair-resolve ----------------
__global__ __launch_bounds__(256, 4) void vq_map(
    const float* __restrict__ x, const float* __restrict__ emb,
    float* __restrict__ out, int n)
{
    __shared__ unsigned char slut[NBINS];
    __shared__ float scoef[(KC - 1) * DC + (KC - 1)];   // 44: full-fallback coeffs
    __shared__ float pcoef[10 * 11];                    // pair diff-poly coeffs
    __shared__ float pAB[20];                           // winner indices as floats

    {
        const uint4* src = (const uint4*)g_lut;
        uint4* dst = (uint4*)slut;
        #pragma unroll
        for (int i = threadIdx.x; i < NBINS / 16; i += 256) dst[i] = src[i];
    }
    {
        int t = threadIdx.x;
        if (t < (KC - 1) * DC) {
            int k = t / DC + 1, j = t % DC;
            scoef[t] = -2.0f * (emb[k * DC + j] - emb[j]);
        } else if (t < (KC - 1) * DC + (KC - 1)) {
            int k = t - (KC - 1) * DC + 1;
            float sk = 0.0f, s0 = 0.0f;
            #pragma unroll
            for (int i = 0; i < DC; i++) {
                float ek = emb[k * DC + i], e0 = emb[i];
                sk = fmaf(ek, ek, sk);
                s0 = fmaf(e0, e0, s0);
            }
            scoef[t] = sk - s0;
        }
        // pair coeffs: 110 entries, layout pcoef[p*11 + j], j<10 power coeffs, j==10 const
        int u = t - 64;
        if (u >= 0 && u < 110) {
            int p = u / 11, j = u % 11;
            int a = PAIR_A[p], b = PAIR_B[p];
            if (j < DC) {
                pcoef[u] = -2.0f * (emb[a * DC + j] - emb[b * DC + j]);
            } else {
                float sa = 0.0f, sb = 0.0f;
                #pragma unroll
                for (int i = 0; i < DC; i++) {
                    float ea = emb[a * DC + i], eb = emb[b * DC + i];
                    sa = fmaf(ea, ea, sa);
                    sb = fmaf(eb, eb, sb);
                }
                pcoef[u] = sa - sb;
            }
        }
        if (t >= 192 && t < 202) {
            int p = t - 192;
            pAB[2 * p]     = (float)PAIR_A[p];
            pAB[2 * p + 1] = (float)PAIR_B[p];
        }
    }
    __syncthreads();

    auto full_fallback = [&](float v) -> float {
        float g[KC - 1];
        #pragma unroll
        for (int k = 0; k < KC - 1; k++) {
            float h = scoef[k * DC + DC - 1];
            #pragma unroll
            for (int j = DC - 2; j >= 0; j--) h = fmaf(h, v, scoef[k * DC + j]);
            g[k] = fmaf(h, v, scoef[(KC - 1) * DC + k]);
        }
        return select_idx(g[0], g[1], g[2], g[3]);
    };

    auto resolve = [&](unsigned code, float v) -> float {
        if (code == 255u) return full_fallback(v);
        int p = (int)code - 128;
        const float* pb = &pcoef[p * 11];
        float h = pb[DC - 1];
        #pragma unroll
        for (int j = DC - 2; j >= 0; j--) h = fmaf(h, v, pb[j]);
        float delta = fmaf(h, v, pb[DC]);          // g_kA - g_kB
        return (delta <= 0.0f) ? pAB[2 * p] : pAB[2 * p + 1];  // tie -> lower index
    };

    auto lookup = [&](float v) -> unsigned {
        int b = (int)(v * (float)NBINS);
        b = max(b, 0);
        b = min(b, NBINS - 1);
        return (unsigned)slut[b];
    };

    const int n4 = n >> 2;
    const float4* __restrict__ x4 = (const float4*)x;
    float4* __restrict__ o4 = (float4*)out;
    const int stride = gridDim.x * blockDim.x;
    const int tid0 = blockIdx.x * blockDim.x + threadIdx.x;

    for (int i = tid0; i < n4; i += stride) {
        float4 a = x4[i];
        unsigned c0 = lookup(a.x);
        unsigned c1 = lookup(a.y);
        unsigned c2 = lookup(a.z);
        unsigned c3 = lookup(a.w);

        float r0 = (float)c0, r1 = (float)c1, r2 = (float)c2, r3 = (float)c3;
        if ((c0 | c1 | c2 | c3) & 0x80u) {
            if (c0 & 0x80u) r0 = resolve(c0, a.x);
            if (c1 & 0x80u) r1 = resolve(c1, a.y);
            if (c2 & 0x80u) r2 = resolve(c2, a.z);
            if (c3 & 0x80u) r3 = resolve(c3, a.w);
        }
        o4[i] = make_float4(r0, r1, r2, r3);
    }

    for (int t = (n4 << 2) + tid0; t < n; t += stride)
        out[t] = full_fallback(x[t]);
}

extern "C" void kernel_launch(void* const* d_in, const int* in_sizes, int n_in,
                              void* d_out, int out_size)
{
    const float* x   = (const float*)d_in[0];
    const float* emb = (const float*)d_in[1];
    if (n_in >= 2 && in_sizes[0] == KC * DC && in_sizes[1] != KC * DC) {
        x   = (const float*)d_in[1];
        emb = (const float*)d_in[0];
    }
    float* out = (float*)d_out;
    int n = out_size;

    vq_build_lut<<<NBINS / 256, 256>>>(emb);
    vq_map<<<592, 256>>>(x, emb, out, n);   // 4 CTAs/SM, one wave
}

// round 12
// speedup vs baseline: 2.8954x; 1.0257x over previous
#include <cuda_runtime.h>

static constexpr int KC = 5;
static constexpr int DC = 10;
static constexpr int NBINS = 8192;
static constexpr float EPS_MARGIN = 2e-5f;

__device__ unsigned char g_lut[NBINS];

__device__ __constant__ int PAIR_A[10] = {0,0,0,0,1,1,1,2,2,3};
__device__ __constant__ int PAIR_B[10] = {1,2,3,4,2,3,4,3,4,4};
__device__ __constant__ int PAIR_OFF[4] = {0,4,7,9};   // p = OFF[kA]+kB-kA-1

// ---------------- Kernel A: LUT builder with pair classification ----------------
__global__ __launch_bounds__(256) void vq_build_lut(const float* __restrict__ emb)
{
    int bin = blockIdx.x * blockDim.x + threadIdx.x;
    if (bin >= NBINS) return;

    float c[KC - 1][DC], d[KC - 1];
    {
        float e0[DC], s0 = 0.0f;
        #pragma unroll
        for (int i = 0; i < DC; i++) { e0[i] = emb[i]; s0 = fmaf(e0[i], e0[i], s0); }
        #pragma unroll
        for (int k = 1; k < KC; k++) {
            float sk = 0.0f;
            #pragma unroll
            for (int i = 0; i < DC; i++) {
                float e = emb[k * DC + i];
                sk = fmaf(e, e, sk);
                c[k - 1][i] = -2.0f * (e - e0[i]);
            }
            d[k - 1] = sk - s0;
        }
    }

    // 7 dilated samples over [bin-0.25, bin+1.25]
    const float offs[7] = {-0.25f, 0.0f, 0.25f, 0.5f, 0.75f, 1.0f, 1.25f};
    float S[7][KC];
    unsigned mask = 0;
    #pragma unroll
    for (int t = 0; t < 7; t++) {
        float v = ((float)bin + offs[t]) * (1.0f / (float)NBINS);
        S[t][0] = 0.0f;
        #pragma unroll
        for (int k = 0; k < KC - 1; k++) {
            float h = c[k][DC - 1];
            #pragma unroll
            for (int j = DC - 2; j >= 0; j--) h = fmaf(h, v, c[k][j]);
            S[t][k + 1] = fmaf(h, v, d[k]);
        }
        int w = 0; float best = S[t][0];
        #pragma unroll
        for (int k = 1; k < KC; k++) if (S[t][k] < best) { best = S[t][k]; w = k; }
        int r = -1; float sec = 3.4e38f;
        #pragma unroll
        for (int k = 0; k < KC; k++)
            if (k != w && S[t][k] < sec) { sec = S[t][k]; r = k; }
        mask |= 1u << w;
        if (sec - best <= EPS_MARGIN) mask |= 1u << r;   // runner-up within margin
    }

    unsigned char byte = 255;
    int pc = __popc(mask);
    if (bin == 0 || bin == NBINS - 1) {
        byte = 255;                                       // edges: exact path
    } else if (pc == 1) {
        byte = (unsigned char)(__ffs(mask) - 1);          // definite winner
    } else if (pc == 2) {
        int kA = __ffs(mask) - 1;
        int kB = 31 - __clz(mask);
        bool ok = true;
        #pragma unroll
        for (int t = 0; t < 7; t++) {
            float minIn = fminf(S[t][kA], S[t][kB]);
            float minOut = 3.4e38f;
            #pragma unroll
            for (int k = 0; k < KC; k++)
                if (!(mask & (1u << k))) minOut = fminf(minOut, S[t][k]);
            ok = ok && (minOut - minIn > EPS_MARGIN);
        }
        if (ok) byte = (unsigned char)(128 + PAIR_OFF[kA] + kB - kA - 1);
    }
    g_lut[bin] = byte;
}

// ---------------- Rare full fallback: out of line to protect hot-path regs ----------------
__device__ __noinline__ float vq_full_fallback(float v, const float* scoef) {
    float g[KC - 1];
    #pragma unroll
    for (int k = 0; k < KC - 1; k++) {
        float h = scoef[k * DC + DC - 1];
        #pragma unroll
        for (int j = DC - 2; j >= 0; j--) h = fmaf(h, v, scoef[k * DC + j]);
        g[k] = fmaf(h, v, scoef[(KC - 1) * DC + k]);
    }
    float best = 0.0f, idx = 0.0f;
    idx = (g[0] < best) ? 1.0f : idx;  best = fminf(g[0], best);
    idx = (g[1] < best) ? 2.0f : idx;  best = fminf(g[1], best);
    idx = (g[2] < best) ? 3.0f : idx;  best = fminf(g[2], best);
    idx = (g[3] < best) ? 4.0f : idx;  best = fminf(g[3], best);
    return idx;
}

// ---------------- Kernel B: LUT-mapped quantize, 128 thr, 9 CTA/SM ----------------
__global__ __launch_bounds__(128, 9) void vq_map(
    const float* __restrict__ x, const float* __restrict__ emb,
    float* __restrict__ out, int n)
{
    __shared__ unsigned char slut[NBINS];                // 8 KB
    __shared__ float scoef[(KC - 1) * DC + (KC - 1)];    // 44
    __shared__ float pcoef[10 * 11];                     // 110
    __shared__ float pAB[20];

    {
        const uint4* src = (const uint4*)g_lut;
        uint4* dst = (uint4*)slut;
        #pragma unroll
        for (int i = threadIdx.x; i < NBINS / 16; i += 128) dst[i] = src[i];
    }
    for (int t = threadIdx.x; t < 44; t += 128) {
        if (t < (KC - 1) * DC) {
            int k = t / DC + 1, j = t % DC;
            scoef[t] = -2.0f * (emb[k * DC + j] - emb[j]);
        } else {
            int k = t - (KC - 1) * DC + 1;
            float sk = 0.0f, s0 = 0.0f;
            #pragma unroll
            for (int i = 0; i < DC; i++) {
                float ek = emb[k * DC + i], e0 = emb[i];
                sk = fmaf(ek, ek, sk);
                s0 = fmaf(e0, e0, s0);
            }
            scoef[t] = sk - s0;
        }
    }
    for (int u = threadIdx.x; u < 110; u += 128) {
        int p = u / 11, j = u % 11;
        int a = PAIR_A[p], b = PAIR_B[p];
        if (j < DC) {
            pcoef[u] = -2.0f * (emb[a * DC + j] - emb[b * DC + j]);
        } else {
            float sa = 0.0f, sb = 0.0f;
            #pragma unroll
            for (int i = 0; i < DC; i++) {
                float ea = emb[a * DC + i], eb = emb[b * DC + i];
                sa = fmaf(ea, ea, sa);
                sb = fmaf(eb, eb, sb);
            }
            pcoef[u] = sa - sb;
        }
    }
    for (int p = threadIdx.x; p < 10; p += 128) {
        pAB[2 * p]     = (float)PAIR_A[p];
        pAB[2 * p + 1] = (float)PAIR_B[p];
    }
    __syncthreads();

    auto resolve = [&](unsigned code, float v) -> float {
        if (code == 255u) return vq_full_fallback(v, scoef);
        int p = (int)code - 128;
        const float* pb = &pcoef[p * 11];
        float h = pb[DC - 1];
        #pragma unroll
        for (int j = DC - 2; j >= 0; j--) h = fmaf(h, v, pb[j]);
        float delta = fmaf(h, v, pb[DC]);                 // g_kA - g_kB
        return (delta <= 0.0f) ? pAB[2 * p] : pAB[2 * p + 1];  // tie -> lower idx
    };

    auto lookup = [&](float v) -> unsigned {
        int b = (int)(v * (float)NBINS);
        b = max(b, 0);
        b = min(b, NBINS - 1);
        return (unsigned)slut[b];
    };

    const int n4 = n >> 2;
    const float4* __restrict__ x4 = (const float4*)x;
    float4* __restrict__ o4 = (float4*)out;
    const int stride = gridDim.x * blockDim.x;
    const int tid0 = blockIdx.x * blockDim.x + threadIdx.x;

    for (int i = tid0; i < n4; i += stride) {
        float4 a = x4[i];
        unsigned c0 = lookup(a.x);
        unsigned c1 = lookup(a.y);
        unsigned c2 = lookup(a.z);
        unsigned c3 = lookup(a.w);

        float r0 = (float)c0, r1 = (float)c1, r2 = (float)c2, r3 = (float)c3;
        if ((c0 | c1 | c2 | c3) & 0x80u) {
            if (c0 & 0x80u) r0 = resolve(c0, a.x);
            if (c1 & 0x80u) r1 = resolve(c1, a.y);
            if (c2 & 0x80u) r2 = resolve(c2, a.z);
            if (c3 & 0x80u) r3 = resolve(c3, a.w);
        }
        o4[i] = make_float4(r0, r1, r2, r3);
    }

    for (int t = (n4 << 2) + tid0; t < n; t += stride)
        out[t] = vq_full_fallback(x[t], scoef);
}

extern "C" void kernel_launch(void* const* d_in, const int* in_sizes, int n_in,
                              void* d_out, int out_size)
{
    const float* x   = (const float*)d_in[0];
    const float* emb = (const float*)d_in[1];
    if (n_in >= 2 && in_sizes[0] == KC * DC && in_sizes[1] != KC * DC) {
        x   = (const float*)d_in[1];
        emb = (const float*)d_in[0];
    }
    float* out = (float*)d_out;
    int n = out_size;

    vq_build_lut<<<NBINS / 256, 256>>>(emb);
    vq_map<<<1332, 128>>>(x, emb, out, n);   // 9 CTAs/SM, one wave
}

// round 13
// speedup vs baseline: 3.1551x; 1.0897x over previous
#include <cuda_runtime.h>

static constexpr int KC = 5;
static constexpr int DC = 10;
static constexpr int NBINS = 8192;
static constexpr float EPS_MARGIN = 2e-5f;

__device__ unsigned char g_lut[NBINS];

__device__ __constant__ int PAIR_A[10] = {0,0,0,0,1,1,1,2,2,3};
__device__ __constant__ int PAIR_B[10] = {1,2,3,4,2,3,4,3,4,4};
__device__ __constant__ int PAIR_OFF[4] = {0,4,7,9};   // p = OFF[kA]+kB-kA-1

// ---------------- Kernel A: LUT builder with pair classification ----------------
__global__ __launch_bounds__(256) void vq_build_lut(const float* __restrict__ emb)
{
    int bin = blockIdx.x * blockDim.x + threadIdx.x;
    if (bin >= NBINS) return;

    float c[KC - 1][DC], d[KC - 1];
    {
        float e0[DC], s0 = 0.0f;
        #pragma unroll
        for (int i = 0; i < DC; i++) { e0[i] = emb[i]; s0 = fmaf(e0[i], e0[i], s0); }
        #pragma unroll
        for (int k = 1; k < KC; k++) {
            float sk = 0.0f;
            #pragma unroll
            for (int i = 0; i < DC; i++) {
                float e = emb[k * DC + i];
                sk = fmaf(e, e, sk);
                c[k - 1][i] = -2.0f * (e - e0[i]);
            }
            d[k - 1] = sk - s0;
        }
    }

    // 7 dilated samples over [bin-0.25, bin+1.25]
    const float offs[7] = {-0.25f, 0.0f, 0.25f, 0.5f, 0.75f, 1.0f, 1.25f};
    float S[7][KC];
    unsigned mask = 0;
    #pragma unroll
    for (int t = 0; t < 7; t++) {
        float v = ((float)bin + offs[t]) * (1.0f / (float)NBINS);
        S[t][0] = 0.0f;
        #pragma unroll
        for (int k = 0; k < KC - 1; k++) {
            float h = c[k][DC - 1];
            #pragma unroll
            for (int j = DC - 2; j >= 0; j--) h = fmaf(h, v, c[k][j]);
            S[t][k + 1] = fmaf(h, v, d[k]);
        }
        int w = 0; float best = S[t][0];
        #pragma unroll
        for (int k = 1; k < KC; k++) if (S[t][k] < best) { best = S[t][k]; w = k; }
        int r = -1; float sec = 3.4e38f;
        #pragma unroll
        for (int k = 0; k < KC; k++)
            if (k != w && S[t][k] < sec) { sec = S[t][k]; r = k; }
        mask |= 1u << w;
        if (sec - best <= EPS_MARGIN) mask |= 1u << r;   // runner-up within margin
    }

    unsigned char byte = 255;
    int pc = __popc(mask);
    if (bin == 0 || bin == NBINS - 1) {
        byte = 255;                                       // edges: exact path
    } else if (pc == 1) {
        byte = (unsigned char)(__ffs(mask) - 1);          // definite winner
    } else if (pc == 2) {
        int kA = __ffs(mask) - 1;
        int kB = 31 - __clz(mask);
        bool ok = true;
        #pragma unroll
        for (int t = 0; t < 7; t++) {
            float minIn = fminf(S[t][kA], S[t][kB]);
            float minOut = 3.4e38f;
            #pragma unroll
            for (int k = 0; k < KC; k++)
                if (!(mask & (1u << k))) minOut = fminf(minOut, S[t][k]);
            ok = ok && (minOut - minIn > EPS_MARGIN);
        }
        if (ok) byte = (unsigned char)(128 + PAIR_OFF[kA] + kB - kA - 1);
    }
    g_lut[bin] = byte;
}

// ---------------- Rare full fallback: out of line to protect hot-path regs ----------------
__device__ __noinline__ float vq_full_fallback(float v, const float* scoef) {
    float g[KC - 1];
    #pragma unroll
    for (int k = 0; k < KC - 1; k++) {
        float h = scoef[k * DC + DC - 1];
        #pragma unroll
        for (int j = DC - 2; j >= 0; j--) h = fmaf(h, v, scoef[k * DC + j]);
        g[k] = fmaf(h, v, scoef[(KC - 1) * DC + k]);
    }
    float best = 0.0f, idx = 0.0f;
    idx = (g[0] < best) ? 1.0f : idx;  best = fminf(g[0], best);
    idx = (g[1] < best) ? 2.0f : idx;  best = fminf(g[1], best);
    idx = (g[2] < best) ? 3.0f : idx;  best = fminf(g[2], best);
    idx = (g[3] < best) ? 4.0f : idx;  best = fminf(g[3], best);
    return idx;
}

// ---------------- Kernel B: LUT map, depth-2 register pipeline ----------------
__global__ __launch_bounds__(128, 7) void vq_map(
    const float* __restrict__ x, const float* __restrict__ emb,
    float* __restrict__ out, int n)
{
    __shared__ unsigned char slut[NBINS];                // 8 KB
    __shared__ float scoef[(KC - 1) * DC + (KC - 1)];    // 44
    __shared__ float pcoef[10 * 11];                     // 110
    __shared__ float pAB[20];

    {
        const uint4* src = (const uint4*)g_lut;
        uint4* dst = (uint4*)slut;
        #pragma unroll
        for (int i = threadIdx.x; i < NBINS / 16; i += 128) dst[i] = src[i];
    }
    for (int t = threadIdx.x; t < 44; t += 128) {
        if (t < (KC - 1) * DC) {
            int k = t / DC + 1, j = t % DC;
            scoef[t] = -2.0f * (emb[k * DC + j] - emb[j]);
        } else {
            int k = t - (KC - 1) * DC + 1;
            float sk = 0.0f, s0 = 0.0f;
            #pragma unroll
            for (int i = 0; i < DC; i++) {
                float ek = emb[k * DC + i], e0 = emb[i];
                sk = fmaf(ek, ek, sk);
                s0 = fmaf(e0, e0, s0);
            }
            scoef[t] = sk - s0;
        }
    }
    for (int u = threadIdx.x; u < 110; u += 128) {
        int p = u / 11, j = u % 11;
        int a = PAIR_A[p], b = PAIR_B[p];
        if (j < DC) {
            pcoef[u] = -2.0f * (emb[a * DC + j] - emb[b * DC + j]);
        } else {
            float sa = 0.0f, sb = 0.0f;
            #pragma unroll
            for (int i = 0; i < DC; i++) {
                float ea = emb[a * DC + i], eb = emb[b * DC + i];
                sa = fmaf(ea, ea, sa);
                sb = fmaf(eb, eb, sb);
            }
            pcoef[u] = sa - sb;
        }
    }
    for (int p = threadIdx.x; p < 10; p += 128) {
        pAB[2 * p]     = (float)PAIR_A[p];
        pAB[2 * p + 1] = (float)PAIR_B[p];
    }
    __syncthreads();

    auto resolve = [&](unsigned code, float v) -> float {
        if (code == 255u) return vq_full_fallback(v, scoef);
        int p = (int)code - 128;
        const float* pb = &pcoef[p * 11];
        float h = pb[DC - 1];
        #pragma unroll
        for (int j = DC - 2; j >= 0; j--) h = fmaf(h, v, pb[j]);
        float delta = fmaf(h, v, pb[DC]);                 // g_kA - g_kB
        return (delta <= 0.0f) ? pAB[2 * p] : pAB[2 * p + 1];  // tie -> lower idx
    };

    auto lookup = [&](float v) -> unsigned {
        int b = (int)(v * (float)NBINS);
        b = max(b, 0);
        b = min(b, NBINS - 1);
        return (unsigned)slut[b];
    };

    const int n4 = n >> 2;
    const float4* __restrict__ x4 = (const float4*)x;
    float4* __restrict__ o4 = (float4*)out;
    const int stride = gridDim.x * blockDim.x;
    int i = blockIdx.x * blockDim.x + threadIdx.x;

    // Depth-2 circular register pipeline: two LDG.128 in flight per warp.
    float4 b0, b1;
    if (i < n4)           b0 = x4[i];
    if (i + stride < n4)  b1 = x4[i + stride];

    for (; i < n4; i += stride) {
        int ip2 = i + 2 * stride;
        float4 nxt;
        if (ip2 < n4) nxt = x4[ip2];       // issued before the dependent chain

        unsigned c0 = lookup(b0.x);
        unsigned c1 = lookup(b0.y);
        unsigned c2 = lookup(b0.z);
        unsigned c3 = lookup(b0.w);

        float r0 = (float)c0, r1 = (float)c1, r2 = (float)c2, r3 = (float)c3;
        if ((c0 | c1 | c2 | c3) & 0x80u) {
            if (c0 & 0x80u) r0 = resolve(c0, b0.x);
            if (c1 & 0x80u) r1 = resolve(c1, b0.y);
            if (c2 & 0x80u) r2 = resolve(c2, b0.z);
            if (c3 & 0x80u) r3 = resolve(c3, b0.w);
        }
        o4[i] = make_float4(r0, r1, r2, r3);

        b0 = b1;
        b1 = nxt;
    }

    for (int t = (n4 << 2) + blockIdx.x * blockDim.x + threadIdx.x; t < n; t += stride)
        out[t] = vq_full_fallback(x[t], scoef);
}

extern "C" void kernel_launch(void* const* d_in, const int* in_sizes, int n_in,
                              void* d_out, int out_size)
{
    const float* x   = (const float*)d_in[0];
    const float* emb = (const float*)d_in[1];
    if (n_in >= 2 && in_sizes[0] == KC * DC && in_sizes[1] != KC * DC) {
        x   = (const float*)d_in[1];
        emb = (const float*)d_in[0];
    }
    float* out = (float*)d_out;
    int n = out_size;

    vq_build_lut<<<NBINS / 256, 256>>>(emb);
    vq_map<<<1036, 128>>>(x, emb, out, n);   // 7 CTAs/SM, one wave
}